// round 1
// baseline (speedup 1.0000x reference)
#include <cuda_runtime.h>

#define HIDDEN      512
#define NUM_LAYERS  8
#define BATCH       16384
#define NUM_OUTPUTS 16

// Scratch (allocation-free rule: __device__ globals)
__device__ float g_wt[NUM_LAYERS * HIDDEN * HIDDEN];  // 8 MB: transposed, pre-scaled weights [l][i][o]
__device__ float g_x0[BATCH * HIDDEN];                // 33.5 MB ping
__device__ float g_x1[BATCH * HIDDEN];                // 33.5 MB pong

// ---------------------------------------------------------------------------
// Pixel norm: x = z * rsqrt(mean(z^2, dim=1) + 1e-8). One warp per row.
// ---------------------------------------------------------------------------
__global__ void pixnorm_kernel(const float* __restrict__ z, float* __restrict__ out) {
    int row  = blockIdx.x * 8 + threadIdx.y;
    int lane = threadIdx.x;
    const float4* zr = (const float4*)(z + (size_t)row * HIDDEN);
    float4 v[4];
    float ss = 0.f;
#pragma unroll
    for (int i = 0; i < 4; i++) {
        v[i] = zr[lane + 32 * i];
        ss += v[i].x * v[i].x + v[i].y * v[i].y + v[i].z * v[i].z + v[i].w * v[i].w;
    }
#pragma unroll
    for (int o = 16; o > 0; o >>= 1) ss += __shfl_xor_sync(0xffffffff, ss, o);
    float s = rsqrtf(ss * (1.0f / 512.0f) + 1e-8f);
    float4* orow = (float4*)(out + (size_t)row * HIDDEN);
#pragma unroll
    for (int i = 0; i < 4; i++) {
        float4 t = v[i];
        t.x *= s; t.y *= s; t.z *= s; t.w *= s;
        orow[lane + 32 * i] = t;
    }
}

// ---------------------------------------------------------------------------
// Weight prep: g_wt[l][i][o] = w[l][o][i] * (0.01/sqrt(512)). 32x32 smem tiles.
// ---------------------------------------------------------------------------
__global__ void wprep_kernel(const float* __restrict__ w) {
    __shared__ float tile[32][33];
    int l  = blockIdx.z;
    int o0 = blockIdx.x * 32;
    int i0 = blockIdx.y * 32;
    const float* wl = w + (size_t)l * HIDDEN * HIDDEN;
#pragma unroll
    for (int r = threadIdx.y; r < 32; r += 8)
        tile[r][threadIdx.x] = wl[(size_t)(o0 + r) * HIDDEN + i0 + threadIdx.x];
    __syncthreads();
    const float wscale = 0.01f / 22.627416997969522f;  // 0.01 / sqrt(512)
    float* wt = g_wt + (size_t)l * HIDDEN * HIDDEN;
#pragma unroll
    for (int r = threadIdx.y; r < 32; r += 8)
        wt[(size_t)(i0 + r) * HIDDEN + o0 + threadIdx.x] = tile[threadIdx.x][r] * wscale;
}

// ---------------------------------------------------------------------------
// Fused GEMM + bias + lrelu*sqrt(2):
//   C[b][o] = act( sum_i A[b][i] * Wt[i][o] + bias[o]*0.01 )
// Tile 128x128x8, 256 threads, 8x8 micro-tile per thread.
// ---------------------------------------------------------------------------
__global__ __launch_bounds__(256, 2) void gemm_lrelu_kernel(
    const float* __restrict__ A,    // [BATCH, 512]
    const float* __restrict__ Bw,   // [512(i), 512(o)] pre-scaled
    const float* __restrict__ bias, // [512] unscaled
    float* __restrict__ C)          // [BATCH, 512]
{
    const int BM = 128, BN = 128, BK = 8;
    __shared__ float As[BK][BM];
    __shared__ float Bs[BK][BN];

    int tid  = threadIdx.x;
    int cRow = blockIdx.y;  // M tile (128 rows)
    int cCol = blockIdx.x;  // N tile (128 cols)

    const float* Ag = A + (size_t)cRow * BM * HIDDEN;
    const float* Bg = Bw + cCol * BN;

    float acc[8][8];
#pragma unroll
    for (int i = 0; i < 8; i++)
#pragma unroll
        for (int j = 0; j < 8; j++) acc[i][j] = 0.f;

    int aRow  = tid >> 1;          // 0..127
    int aCol4 = (tid & 1) * 4;     // 0 or 4
    int bRow  = tid >> 5;          // 0..7
    int bCol4 = (tid & 31) * 4;    // 0..124
    int tr = (tid >> 4) * 8;       // thread micro-tile row
    int tc = (tid & 15) * 8;       // thread micro-tile col

    for (int k0 = 0; k0 < HIDDEN; k0 += BK) {
        float4 av = *(const float4*)(Ag + (size_t)aRow * HIDDEN + k0 + aCol4);
        float4 bv = *(const float4*)(Bg + (size_t)(k0 + bRow) * HIDDEN + bCol4);
        As[aCol4 + 0][aRow] = av.x;
        As[aCol4 + 1][aRow] = av.y;
        As[aCol4 + 2][aRow] = av.z;
        As[aCol4 + 3][aRow] = av.w;
        *(float4*)&Bs[bRow][bCol4] = bv;
        __syncthreads();
#pragma unroll
        for (int kk = 0; kk < BK; kk++) {
            float a[8], b[8];
            *(float4*)&a[0] = *(const float4*)&As[kk][tr];
            *(float4*)&a[4] = *(const float4*)&As[kk][tr + 4];
            *(float4*)&b[0] = *(const float4*)&Bs[kk][tc];
            *(float4*)&b[4] = *(const float4*)&Bs[kk][tc + 4];
#pragma unroll
            for (int i = 0; i < 8; i++)
#pragma unroll
                for (int j = 0; j < 8; j++)
                    acc[i][j] += a[i] * b[j];
        }
        __syncthreads();
    }

    const float bscale = 0.01f;
    const float gain   = 1.41421356237309515f;  // sqrt(2)
    float bcol[8];
#pragma unroll
    for (int j = 0; j < 8; j++) bcol[j] = bias[cCol * BN + tc + j] * bscale;

    float* Cg = C + (size_t)cRow * BM * HIDDEN + cCol * BN;
#pragma unroll
    for (int i = 0; i < 8; i++) {
#pragma unroll
        for (int j = 0; j < 8; j++) {
            float v = acc[i][j] + bcol[j];
            v = (v > 0.f ? v : 0.2f * v) * gain;
            acc[i][j] = v;
        }
        *(float4*)(Cg + (size_t)(tr + i) * HIDDEN + tc)     = *(float4*)&acc[i][0];
        *(float4*)(Cg + (size_t)(tr + i) * HIDDEN + tc + 4) = *(float4*)&acc[i][4];
    }
}

// ---------------------------------------------------------------------------
// Broadcast: out[b][j][c] = x[b][c] for j in [0,16)
// ---------------------------------------------------------------------------
__global__ void bcast_kernel(const float* __restrict__ x, float* __restrict__ out) {
    int row = blockIdx.x;
    int t   = threadIdx.x;  // 0..127 (float4 index within row)
    float4 v = ((const float4*)(x + (size_t)row * HIDDEN))[t];
    float4* o = (float4*)(out + (size_t)row * NUM_OUTPUTS * HIDDEN);
#pragma unroll
    for (int j = 0; j < NUM_OUTPUTS; j++)
        o[j * (HIDDEN / 4) + t] = v;
}

// ---------------------------------------------------------------------------
extern "C" void kernel_launch(void* const* d_in, const int* in_sizes, int n_in,
                              void* d_out, int out_size) {
    const float* z    = (const float*)d_in[0];
    const float* w    = (const float*)d_in[1];
    const float* bias = (const float*)d_in[2];
    float* out = (float*)d_out;

    float *gx0, *gx1, *gwt;
    cudaGetSymbolAddress((void**)&gx0, g_x0);
    cudaGetSymbolAddress((void**)&gx1, g_x1);
    cudaGetSymbolAddress((void**)&gwt, g_wt);

    // 1) weight transpose + scale
    wprep_kernel<<<dim3(16, 16, 8), dim3(32, 8)>>>(w);
    // 2) pixel norm
    pixnorm_kernel<<<BATCH / 8, dim3(32, 8)>>>(z, gx0);
    // 3) 8 fused dense layers, ping-pong
    float* cur = gx0;
    float* nxt = gx1;
    for (int l = 0; l < NUM_LAYERS; l++) {
        gemm_lrelu_kernel<<<dim3(HIDDEN / 128, BATCH / 128), 256>>>(
            cur, gwt + (size_t)l * HIDDEN * HIDDEN, bias + l * HIDDEN, nxt);
        float* t = cur; cur = nxt; nxt = t;
    }
    // after 8 layers (even), result is back in gx0 -> 'cur'
    // 4) broadcast to 16 outputs
    bcast_kernel<<<BATCH, HIDDEN / 4>>>(cur, out);
}

// round 3
// speedup vs baseline: 2.2648x; 2.2648x over previous
#include <cuda_runtime.h>
#include <cuda_bf16.h>
#include <cstdint>

#define HIDDEN      512
#define NUM_LAYERS  8
#define BATCH       16384
#define NUM_OUTPUTS 16

// ---------------- device scratch (allocation-free rule) ----------------
__device__ __nv_bfloat16 g_whi[NUM_LAYERS * HIDDEN * HIDDEN];  // 4 MB
__device__ __nv_bfloat16 g_wlo[NUM_LAYERS * HIDDEN * HIDDEN];  // 4 MB
__device__ __nv_bfloat16 g_ahi[2][BATCH * HIDDEN];             // 2x16 MB
__device__ __nv_bfloat16 g_alo[2][BATCH * HIDDEN];             // 2x16 MB

// ---------------- helpers ----------------
__device__ __forceinline__ uint32_t smem_u32(const void* p) {
    return (uint32_t)__cvta_generic_to_shared(p);
}

#define CP_ASYNC16(dst, src) \
    asm volatile("cp.async.cg.shared.global [%0], [%1], 16;" :: "r"(dst), "l"(src))
#define CP_COMMIT() asm volatile("cp.async.commit_group;" ::: "memory")

#define LDSM_X4(r, addr)                                                        \
    asm volatile("ldmatrix.sync.aligned.m8n8.x4.shared.b16 {%0,%1,%2,%3}, [%4];"\
        : "=r"((r)[0]), "=r"((r)[1]), "=r"((r)[2]), "=r"((r)[3]) : "r"(addr))
#define LDSM_X2(r, addr)                                                        \
    asm volatile("ldmatrix.sync.aligned.m8n8.x2.shared.b16 {%0,%1}, [%2];"      \
        : "=r"((r)[0]), "=r"((r)[1]) : "r"(addr))

#define MMA16816(d, a, b)                                                       \
    asm volatile("mma.sync.aligned.m16n8k16.row.col.f32.bf16.bf16.f32 "         \
        "{%0,%1,%2,%3},{%4,%5,%6,%7},{%8,%9},{%0,%1,%2,%3};"                    \
        : "+f"((d)[0]), "+f"((d)[1]), "+f"((d)[2]), "+f"((d)[3])                \
        : "r"((a)[0]), "r"((a)[1]), "r"((a)[2]), "r"((a)[3]),                   \
          "r"((b)[0]), "r"((b)[1]))

__device__ __forceinline__ uint32_t pk2(float a, float b) {
    __nv_bfloat162 t = __floats2bfloat162_rn(a, b);
    return *reinterpret_cast<uint32_t*>(&t);
}
__device__ __forceinline__ void split_pack(float a, float b, uint32_t& hp, uint32_t& lp) {
    __nv_bfloat16 ha = __float2bfloat16_rn(a);
    __nv_bfloat16 hb = __float2bfloat16_rn(b);
    __nv_bfloat162 H = __halves2bfloat162(ha, hb);
    hp = *reinterpret_cast<uint32_t*>(&H);
    lp = pk2(a - __bfloat162float(ha), b - __bfloat162float(hb));
}

// ---------------- weight prep: split W*wscale into bf16 hi/lo ----------------
__global__ void wprep_kernel(const float* __restrict__ w,
                             __nv_bfloat16* __restrict__ whi,
                             __nv_bfloat16* __restrict__ wlo) {
    size_t base = ((size_t)blockIdx.x * 256 + threadIdx.x) * 4;
    const float ws = 4.4194173824159216e-4f;  // 0.01 / sqrt(512)
    float4 v = *(const float4*)(w + base);
    uint2 H, L;
    split_pack(v.x * ws, v.y * ws, H.x, L.x);
    split_pack(v.z * ws, v.w * ws, H.y, L.y);
    *(uint2*)(whi + base) = H;
    *(uint2*)(wlo + base) = L;
}

// ---------------- pixel norm -> bf16 hi/lo ----------------
__global__ void pixnorm_kernel(const float* __restrict__ z,
                               __nv_bfloat16* __restrict__ ohi,
                               __nv_bfloat16* __restrict__ olo) {
    int row  = blockIdx.x * 8 + threadIdx.y;
    int lane = threadIdx.x;
    const float4* zr = (const float4*)(z + (size_t)row * HIDDEN);
    float4 v[4];
    float ss = 0.f;
#pragma unroll
    for (int i = 0; i < 4; i++) {
        v[i] = zr[lane + 32 * i];
        ss += v[i].x * v[i].x + v[i].y * v[i].y + v[i].z * v[i].z + v[i].w * v[i].w;
    }
#pragma unroll
    for (int o = 16; o > 0; o >>= 1) ss += __shfl_xor_sync(0xffffffff, ss, o);
    float s = rsqrtf(ss * (1.0f / 512.0f) + 1e-8f);
#pragma unroll
    for (int i = 0; i < 4; i++) {
        float4 t = v[i];
        t.x *= s; t.y *= s; t.z *= s; t.w *= s;
        uint2 H, L;
        split_pack(t.x, t.y, H.x, L.x);
        split_pack(t.z, t.w, H.y, L.y);
        size_t off = (size_t)row * HIDDEN + 4 * (lane + 32 * i);
        *(uint2*)(ohi + off) = H;
        *(uint2*)(olo + off) = L;
    }
}

// ---------------- HMMA GEMM + bias + lrelu (+ fused bcast on last) ----------
// CTA 128(M)x128(N), K chunks of 32. 8 warps: 2(M)x4(N), warp tile 64x32.
// SMEM: per stage 4 planes [Ahi|Alo|Bhi|Blo], each 128 rows x 32 bf16,
// row stride 80 B (5*16B; 5 coprime 8 -> conflict-free ldmatrix).
#define LDT_B    80
#define PLANE_B  (128 * LDT_B)          // 10240
#define STAGE_B  (4 * PLANE_B)          // 40960
#define SMEM_BYTES (2 * STAGE_B)        // 81920

__global__ __launch_bounds__(256, 2) void gemm_mma_kernel(
    const __nv_bfloat16* __restrict__ Ahi, const __nv_bfloat16* __restrict__ Alo,
    const __nv_bfloat16* __restrict__ Whi, const __nv_bfloat16* __restrict__ Wlo,
    const float* __restrict__ bias,
    __nv_bfloat16* __restrict__ Ohi, __nv_bfloat16* __restrict__ Olo,
    float* __restrict__ outF, int last)
{
    extern __shared__ char smem[];
    const uint32_t sb = smem_u32(smem);
    const int tid  = threadIdx.x;
    const int lane = tid & 31;
    const int warp = tid >> 5;
    const int wm = warp >> 2;       // 0..1
    const int wn = warp & 3;        // 0..3
    const int m0 = blockIdx.y * 128;
    const int n0 = blockIdx.x * 128;

    float acc[4][4][4];
#pragma unroll
    for (int i = 0; i < 4; i++)
#pragma unroll
        for (int j = 0; j < 4; j++)
#pragma unroll
            for (int k = 0; k < 4; k++) acc[i][j][k] = 0.f;

    // ---- async loader: chunk c -> stage s ----
    auto load_chunk = [&](int c, int s) {
        const int k0 = c * 32;
#pragma unroll
        for (int it = 0; it < 8; it++) {
            int o = it * 256 + tid;        // 0..2047
            int plane = o >> 9;            // 0:Ahi 1:Alo 2:Bhi 3:Blo
            int r = (o >> 2) & 127;
            int q = o & 3;
            const __nv_bfloat16* src;
            if      (plane == 0) src = Ahi + (size_t)(m0 + r) * HIDDEN;
            else if (plane == 1) src = Alo + (size_t)(m0 + r) * HIDDEN;
            else if (plane == 2) src = Whi + (size_t)(n0 + r) * HIDDEN;
            else                 src = Wlo + (size_t)(n0 + r) * HIDDEN;
            src += k0 + q * 8;
            uint32_t dst = sb + s * STAGE_B + plane * PLANE_B + r * LDT_B + q * 16;
            CP_ASYNC16(dst, src);
        }
        CP_COMMIT();
    };

    load_chunk(0, 0);
    load_chunk(1, 1);

    const int a_row = lane & 15;
    const int a_kh  = lane >> 4;
    const int b_row = lane & 7;
    const int b_kh  = (lane >> 3) & 1;

    for (int c = 0; c < 16; c++) {
        if (c < 15) asm volatile("cp.async.wait_group 1;" ::: "memory");
        else        asm volatile("cp.async.wait_group 0;" ::: "memory");
        __syncthreads();

        const uint32_t st = sb + (c & 1) * STAGE_B;
#pragma unroll
        for (int ks = 0; ks < 2; ks++) {
            const int kof = ks * 16;
            uint32_t ahi[4][4], alo_[4][4];
#pragma unroll
            for (int mi = 0; mi < 4; mi++) {
                uint32_t ad = st + (uint32_t)(wm * 64 + mi * 16 + a_row) * LDT_B
                                 + (kof + a_kh * 8) * 2;
                LDSM_X4(ahi[mi], ad);
                LDSM_X4(alo_[mi], ad + PLANE_B);
            }
            uint32_t bhi[4][2], blo_[4][2];
#pragma unroll
            for (int ni = 0; ni < 4; ni++) {
                uint32_t bd = st + 2 * PLANE_B
                                 + (uint32_t)(wn * 32 + ni * 8 + b_row) * LDT_B
                                 + (kof + b_kh * 8) * 2;
                LDSM_X2(bhi[ni], bd);
                LDSM_X2(blo_[ni], bd + PLANE_B);
            }
#pragma unroll
            for (int mi = 0; mi < 4; mi++)
#pragma unroll
                for (int ni = 0; ni < 4; ni++) MMA16816(acc[mi][ni], ahi[mi], bhi[ni]);
#pragma unroll
            for (int mi = 0; mi < 4; mi++)
#pragma unroll
                for (int ni = 0; ni < 4; ni++) MMA16816(acc[mi][ni], ahi[mi], blo_[ni]);
#pragma unroll
            for (int mi = 0; mi < 4; mi++)
#pragma unroll
                for (int ni = 0; ni < 4; ni++) MMA16816(acc[mi][ni], alo_[mi], bhi[ni]);
        }
        __syncthreads();
        if (c + 2 < 16) load_chunk(c + 2, c & 1);
    }

    // ---- epilogue ----
    const float gain = 1.41421356237309515f;
    const int t4r = lane >> 2;
    const int t2c = (lane & 3) * 2;
#pragma unroll
    for (int ni = 0; ni < 4; ni++) {
        const int c0 = n0 + wn * 32 + ni * 8 + t2c;
        float2 b2 = *(const float2*)(bias + c0);
        const float bb0 = b2.x * 0.01f, bb1 = b2.y * 0.01f;
#pragma unroll
        for (int mi = 0; mi < 4; mi++) {
            const int r0 = m0 + wm * 64 + mi * 16 + t4r;
            float v0 = acc[mi][ni][0] + bb0;
            float v1 = acc[mi][ni][1] + bb1;
            float v2 = acc[mi][ni][2] + bb0;
            float v3 = acc[mi][ni][3] + bb1;
            v0 = (v0 > 0.f ? v0 : 0.2f * v0) * gain;
            v1 = (v1 > 0.f ? v1 : 0.2f * v1) * gain;
            v2 = (v2 > 0.f ? v2 : 0.2f * v2) * gain;
            v3 = (v3 > 0.f ? v3 : 0.2f * v3) * gain;
            if (!last) {
                uint32_t h01, l01, h23, l23;
                split_pack(v0, v1, h01, l01);
                split_pack(v2, v3, h23, l23);
                *(uint32_t*)(Ohi + (size_t)r0 * HIDDEN + c0)       = h01;
                *(uint32_t*)(Olo + (size_t)r0 * HIDDEN + c0)       = l01;
                *(uint32_t*)(Ohi + (size_t)(r0 + 8) * HIDDEN + c0) = h23;
                *(uint32_t*)(Olo + (size_t)(r0 + 8) * HIDDEN + c0) = l23;
            } else {
                float2 p01 = make_float2(v0, v1);
                float2 p23 = make_float2(v2, v3);
                float* o0 = outF + (size_t)r0 * NUM_OUTPUTS * HIDDEN + c0;
                float* o1 = outF + (size_t)(r0 + 8) * NUM_OUTPUTS * HIDDEN + c0;
#pragma unroll
                for (int j = 0; j < NUM_OUTPUTS; j++) {
                    *(float2*)(o0 + j * HIDDEN) = p01;
                    *(float2*)(o1 + j * HIDDEN) = p23;
                }
            }
        }
    }
}

// ---------------------------------------------------------------------------
extern "C" void kernel_launch(void* const* d_in, const int* in_sizes, int n_in,
                              void* d_out, int out_size) {
    const float* z    = (const float*)d_in[0];
    const float* w    = (const float*)d_in[1];
    const float* bias = (const float*)d_in[2];
    float* out = (float*)d_out;

    __nv_bfloat16 *whi, *wlo, *ahi, *alo;
    cudaGetSymbolAddress((void**)&whi, g_whi);
    cudaGetSymbolAddress((void**)&wlo, g_wlo);
    cudaGetSymbolAddress((void**)&ahi, g_ahi);
    cudaGetSymbolAddress((void**)&alo, g_alo);

    cudaFuncSetAttribute(gemm_mma_kernel,
                         cudaFuncAttributeMaxDynamicSharedMemorySize, SMEM_BYTES);

    // 1) weight split
    wprep_kernel<<<2048, 256>>>(w, whi, wlo);
    // 2) pixel norm + split
    pixnorm_kernel<<<BATCH / 8, dim3(32, 8)>>>(z, ahi, alo);
    // 3) 8 HMMA layers, ping-pong; last fuses broadcast into epilogue
    for (int l = 0; l < NUM_LAYERS; l++) {
        int pi = l & 1, po = pi ^ 1;
        gemm_mma_kernel<<<dim3(HIDDEN / 128, BATCH / 128), 256, SMEM_BYTES>>>(
            ahi + (size_t)pi * BATCH * HIDDEN, alo + (size_t)pi * BATCH * HIDDEN,
            whi + (size_t)l * HIDDEN * HIDDEN, wlo + (size_t)l * HIDDEN * HIDDEN,
            bias + l * HIDDEN,
            ahi + (size_t)po * BATCH * HIDDEN, alo + (size_t)po * BATCH * HIDDEN,
            out, (l == NUM_LAYERS - 1) ? 1 : 0);
    }
}